// round 7
// baseline (speedup 1.0000x reference)
#include <cuda_runtime.h>
#include <cstdint>

// Sliding-window gated attention (W=32, D=64) via tf32 mma.sync (sm_100-compatible).
// Per block: (b, h, 64 queries), 8 warps. Warp pair (g, g+4) shares one 16-query
// group and splits the 48-col band by tiles:
//   GEMM1: each warp 3 of 6 nt tiles  -> S[16,24] each     (24 MMAs)
//   epilogue: gate+mask own cols -> shared W[16,48] tile (aliased over K)
//   GEMM2: each warp 32 of 64 output cols, full 48-K       (24 MMAs, no reduction)

constexpr int B_ = 2, S_ = 2048, H_ = 8, D_ = 64, W_ = 32;
constexpr int HD = H_ * D_;
constexpr int TS   = 64;           // queries per block
constexpr int NT   = 256;          // threads per block (8 warps)
constexpr int ROWS = TS + 32;      // 96 staged k/v rows
constexpr int STRIDE = 68;         // k/v smem row stride (floats), conflict-free
constexpr int WSTR = 52;           // per-group weight tile stride, conflict-free
constexpr float SCALE = 0.125f;

constexpr int OFF_K = 0;                        // aliased by W tiles after GEMM1
constexpr int SZ_K  = ROWS * STRIDE;            // 6528
constexpr int OFF_V = OFF_K + SZ_K;
constexpr int OFF_A = OFF_V + SZ_K;             // ROWS floats
constexpr int SMEM_FLOATS = OFF_A + ROWS;       // 13152 floats = 52608 B

__device__ __forceinline__ float f2tf32(float x) {
    uint32_t r; asm("cvt.rna.tf32.f32 %0, %1;" : "=r"(r) : "f"(x));
    return __uint_as_float(r);
}
__device__ __forceinline__ uint32_t bits(float x) { return __float_as_uint(x); }

__device__ __forceinline__ void mma_tf32(float* d,
                                         uint32_t a0, uint32_t a1, uint32_t a2, uint32_t a3,
                                         uint32_t b0, uint32_t b1) {
    asm volatile("mma.sync.aligned.m16n8k8.row.col.f32.tf32.tf32.f32 "
                 "{%0,%1,%2,%3}, {%4,%5,%6,%7}, {%8,%9}, {%0,%1,%2,%3};"
                 : "+f"(d[0]), "+f"(d[1]), "+f"(d[2]), "+f"(d[3])
                 : "r"(a0), "r"(a1), "r"(a2), "r"(a3), "r"(b0), "r"(b1));
}

__global__ __launch_bounds__(NT, 3)
void swa_mma4_kernel(const float* __restrict__ qg,
                     const float* __restrict__ kg,
                     const float* __restrict__ vg,
                     const float* __restrict__ ag,
                     const float* __restrict__ bg,
                     float* __restrict__ outg)
{
    extern __shared__ float sm[];
    float* ks   = sm + OFF_K;
    float* vs   = sm + OFF_V;
    float* a_sm = sm + OFF_A;

    const int s0  = blockIdx.x * TS;
    const int h   = blockIdx.y;
    const int bb  = blockIdx.z;
    const int tid = threadIdx.x;
    const int warp = tid >> 5;
    const int lane = tid & 31;
    const int gid  = lane >> 2;      // fragment row-in-group
    const int tig  = lane & 3;       // thread in group
    const int grp  = warp & 3;       // query group (16 queries)
    const int half = warp >> 2;      // band half (0: nt 0..2 / cols 0..31; 1: nt 3..5 / cols 32..63)
    const int qb   = grp * 16;       // group's first local query
    const size_t headBase = (size_t)bb * S_ * HD + (size_t)h * D_;

    // ---- Q fragments straight from gmem (full k-dim; both halves need all) ----
    const float* qrow0 = qg + headBase + (size_t)(s0 + qb + gid) * HD;
    const float* qrow1 = qrow0 + (size_t)8 * HD;
    uint32_t qa[8][4];
#pragma unroll
    for (int kk = 0; kk < 8; kk++) {
        const int c = kk * 8 + tig;
        qa[kk][0] = bits(f2tf32(qrow0[c]));
        qa[kk][1] = bits(f2tf32(qrow1[c]));
        qa[kk][2] = bits(f2tf32(qrow0[c + 4]));
        qa[kk][3] = bits(f2tf32(qrow1[c + 4]));
    }
    const float bq0 = bg[((size_t)bb * S_ + (s0 + qb + gid)) * H_ + h];
    const float bq1 = bg[((size_t)bb * S_ + (s0 + qb + gid + 8)) * H_ + h];

    // ---- Stage K, V (tf32, zero-fill out-of-range rows) ----
    for (int idx = tid; idx < ROWS * 16; idx += NT) {
        const int r = idx >> 4, c4 = (idx & 15) << 2;
        const int j = s0 - (W_ - 1) + r;
        float4 fk = make_float4(0.f, 0.f, 0.f, 0.f), fv = fk;
        if (j >= 0 && j < S_) {
            const size_t off = headBase + (size_t)j * HD + c4;
            fk = *(const float4*)(kg + off);
            fv = *(const float4*)(vg + off);
        }
        float* dk = ks + r * STRIDE + c4;
        float* dv = vs + r * STRIDE + c4;
        dk[0] = f2tf32(fk.x); dk[1] = f2tf32(fk.y); dk[2] = f2tf32(fk.z); dk[3] = f2tf32(fk.w);
        dv[0] = f2tf32(fv.x); dv[1] = f2tf32(fv.y); dv[2] = f2tf32(fv.z); dv[3] = f2tf32(fv.w);
    }
    for (int r = tid; r < ROWS; r += NT) {
        const int j = s0 - (W_ - 1) + r;
        a_sm[r] = (j >= 0 && j < S_) ? ag[((size_t)bb * S_ + j) * H_ + h] : 0.f;
    }
    __syncthreads();

    // ---- GEMM1: S[16, 24] = Q @ K^T over this warp's 3 nt tiles ----
    float acc[3][4] = {};
#pragma unroll
    for (int kk = 0; kk < 8; kk++) {
#pragma unroll
        for (int t = 0; t < 3; t++) {
            const int nt = half * 3 + t;
            const float* kp = ks + (qb + nt * 8 + gid) * STRIDE + kk * 8 + tig;
            mma_tf32(acc[t], qa[kk][0], qa[kk][1], qa[kk][2], qa[kk][3],
                     bits(kp[0]), bits(kp[4]));
        }
    }
    __syncthreads();   // all K reads done -> W tiles may overwrite K region

    // ---- Gating + band mask; own cols of shared per-group W tile (over K) ----
    float* wsw = ks + grp * (16 * WSTR);
#pragma unroll
    for (int t = 0; t < 3; t++) {
        const int nt = half * 3 + t;
#pragma unroll
        for (int e = 0; e < 4; e++) {
            const int row = (e >= 2) ? gid + 8 : gid;
            const int col = nt * 8 + 2 * tig + (e & 1);
            const int l   = qb + col;
            const int j   = s0 - (W_ - 1) + l;
            const int d   = col - row;
            const bool ok = (d >= 0) && (d < W_) && (j >= 0);
            const float bq = (e >= 2) ? bq1 : bq0;
            const float g = 1.f / (1.f + __expf(-a_sm[l] * bq));
            wsw[row * WSTR + col] = f2tf32(ok ? acc[t][e] * (SCALE * g) : 0.f);
        }
    }
    __syncthreads();   // full W tile visible to both warps of the pair

    // ---- GEMM2: O[16, 32] = W[16,48] @ V[48, own 32 cols] ----
    float oacc[4][4] = {};
#pragma unroll
    for (int kk = 0; kk < 6; kk++) {
        const float* wrow = wsw + gid * WSTR + kk * 8 + tig;
        const uint32_t a0 = bits(wrow[0]);
        const uint32_t a1 = bits(wrow[8 * WSTR]);
        const uint32_t a2 = bits(wrow[4]);
        const uint32_t a3 = bits(wrow[8 * WSTR + 4]);
#pragma unroll
        for (int t = 0; t < 4; t++) {
            const int ntg = half * 4 + t;    // output col tile (0..7)
            const float* vp0 = vs + (qb + kk * 8 + tig) * STRIDE + ntg * 8 + gid;
            const float* vp1 = vp0 + 4 * STRIDE;
            mma_tf32(oacc[t], a0, a1, a2, a3, bits(vp0[0]), bits(vp1[0]));
        }
    }

    // ---- Store O (own 32 columns) ----
    float* d0 = outg + headBase + (size_t)(s0 + qb + gid) * HD + half * 32 + 2 * tig;
    float* d1 = d0 + (size_t)8 * HD;
#pragma unroll
    for (int t = 0; t < 4; t++) {
        *(float2*)(d0 + t * 8) = make_float2(oacc[t][0], oacc[t][1]);
        *(float2*)(d1 + t * 8) = make_float2(oacc[t][2], oacc[t][3]);
    }
}

extern "C" void kernel_launch(void* const* d_in, const int* in_sizes, int n_in,
                              void* d_out, int out_size)
{
    const float* q = (const float*)d_in[0];
    const float* k = (const float*)d_in[1];
    const float* v = (const float*)d_in[2];
    const float* a = (const float*)d_in[3];
    const float* b = (const float*)d_in[4];
    float* out = (float*)d_out;

    const int smem = SMEM_FLOATS * (int)sizeof(float);   // 52608 B
    cudaFuncSetAttribute(swa_mma4_kernel,
                         cudaFuncAttributeMaxDynamicSharedMemorySize, smem);
    dim3 grid(S_ / TS, H_, B_);
    swa_mma4_kernel<<<grid, NT, smem>>>(q, k, v, a, b, out);
}

// round 8
// speedup vs baseline: 1.2788x; 1.2788x over previous
#include <cuda_runtime.h>
#include <cstdint>

// Sliding-window gated attention (W=32, D=64) via tf32 mma.sync (sm_100-compatible).
// Per block: (b, h, 64 queries), 4 warps, each warp 16 queries x 48-col band.
//   stage: cp.async raw K/V -> smem, in-place rna->tf32 convert
//   GEMM1: S[16,48] = Q[16,64] @ K[48,64]^T   (48 m16n8k8, Q frags from gmem)
//   gate:  W = S*SCALE*sigmoid(a_l*b_q)*mask  (registers, D->A frag via shuffles)
//   GEMM2: O[16,64] = W[16,48] @ V[48,64]     (48 m16n8k8, no smem W, no barrier)

constexpr int B_ = 2, S_ = 2048, H_ = 8, D_ = 64, W_ = 32;
constexpr int HD = H_ * D_;
constexpr int TS   = 64;
constexpr int NT   = 128;
constexpr int ROWS = 96;           // 95 needed, 96 for even split
constexpr int STRIDE = 68;         // conflict-free: gid*68+tig mod 32 = gid*4+tig
constexpr float SCALE = 0.125f;

constexpr int OFF_K = 0;
constexpr int SZ_K  = ROWS * STRIDE;            // 6528
constexpr int OFF_V = OFF_K + SZ_K;
constexpr int OFF_A = OFF_V + SZ_K;
constexpr int SMEM_FLOATS = OFF_A + ROWS;       // 13152 floats = 52608 B -> 4 CTAs/SM

__device__ __forceinline__ float f2tf32(float x) {
    uint32_t r; asm("cvt.rna.tf32.f32 %0, %1;" : "=r"(r) : "f"(x));
    return __uint_as_float(r);
}
__device__ __forceinline__ uint32_t bits(float x) { return __float_as_uint(x); }

__device__ __forceinline__ uint32_t smem_u32(const void* p) {
    uint32_t a;
    asm("{ .reg .u64 t; cvta.to.shared.u64 t, %1; cvt.u32.u64 %0, t; }" : "=r"(a) : "l"(p));
    return a;
}
__device__ __forceinline__ void cp16(uint32_t dst, const void* src, int srcsize) {
    asm volatile("cp.async.cg.shared.global [%0], [%1], 16, %2;"
                 :: "r"(dst), "l"(src), "r"(srcsize) : "memory");
}

__device__ __forceinline__ void mma_tf32(float* d,
                                         uint32_t a0, uint32_t a1, uint32_t a2, uint32_t a3,
                                         uint32_t b0, uint32_t b1) {
    asm volatile("mma.sync.aligned.m16n8k8.row.col.f32.tf32.tf32.f32 "
                 "{%0,%1,%2,%3}, {%4,%5,%6,%7}, {%8,%9}, {%0,%1,%2,%3};"
                 : "+f"(d[0]), "+f"(d[1]), "+f"(d[2]), "+f"(d[3])
                 : "r"(a0), "r"(a1), "r"(a2), "r"(a3), "r"(b0), "r"(b1));
}

__global__ __launch_bounds__(NT, 4)
void swa_mma5_kernel(const float* __restrict__ qg,
                     const float* __restrict__ kg,
                     const float* __restrict__ vg,
                     const float* __restrict__ ag,
                     const float* __restrict__ bg,
                     float* __restrict__ outg)
{
    extern __shared__ float sm[];
    float* ks   = sm + OFF_K;
    float* vs   = sm + OFF_V;
    float* a_sm = sm + OFF_A;
    const uint32_t smb = smem_u32(sm);

    const int s0  = blockIdx.x * TS;
    const int h   = blockIdx.y;
    const int bb  = blockIdx.z;
    const int tid = threadIdx.x;
    const int lane = tid & 31;
    const int gid  = lane >> 2;
    const int tig  = lane & 3;
    const int qb   = (tid >> 5) * 16;
    const size_t headBase = (size_t)bb * S_ * HD + (size_t)h * D_;

    // ---- Issue raw K/V staging via cp.async (zero-fill OOB rows) ----
#pragma unroll
    for (int i = 0; i < 12; i++) {
        const int idx = tid + i * NT;          // 0..1535
        const int r = idx >> 4, c4 = (idx & 15) << 2;
        const int j = s0 - (W_ - 1) + r;
        const bool ok = (j >= 0) && (j < S_);
        const int jc = ok ? j : 0;             // clamp for address formation
        const size_t off = headBase + (size_t)jc * HD + c4;
        const int sz = ok ? 16 : 0;
        cp16(smb + (uint32_t)(OFF_K + r * STRIDE + c4) * 4u, kg + off, sz);
        cp16(smb + (uint32_t)(OFF_V + r * STRIDE + c4) * 4u, vg + off, sz);
    }
    asm volatile("cp.async.commit_group;" ::: "memory");

    // ---- Q fragments from gmem (overlap cp.async) ----
    const float* qrow0 = qg + headBase + (size_t)(s0 + qb + gid) * HD;
    const float* qrow1 = qrow0 + (size_t)8 * HD;
    uint32_t qa[8][4];
#pragma unroll
    for (int kk = 0; kk < 8; kk++) {
        const int c = kk * 8 + tig;
        qa[kk][0] = bits(f2tf32(qrow0[c]));
        qa[kk][1] = bits(f2tf32(qrow1[c]));
        qa[kk][2] = bits(f2tf32(qrow0[c + 4]));
        qa[kk][3] = bits(f2tf32(qrow1[c + 4]));
    }
    const float bq0 = bg[((size_t)bb * S_ + (s0 + qb + gid)) * H_ + h];
    const float bq1 = bg[((size_t)bb * S_ + (s0 + qb + gid + 8)) * H_ + h];
    if (tid < ROWS) {
        const int j = s0 - (W_ - 1) + tid;
        a_sm[tid] = (j >= 0 && j < S_) ? ag[((size_t)bb * S_ + j) * H_ + h] : 0.f;
    }

    asm volatile("cp.async.wait_group 0;" ::: "memory");
    __syncthreads();

    // ---- In-place rna->tf32 convert (each element exactly once) ----
#pragma unroll
    for (int i = 0; i < 12; i++) {
        const int idx = tid + i * NT;
        const int r = idx >> 4, c4 = (idx & 15) << 2;
        float4* pk = (float4*)(ks + r * STRIDE + c4);
        float4* pv = (float4*)(vs + r * STRIDE + c4);
        float4 xk = *pk, xv = *pv;
        xk.x = f2tf32(xk.x); xk.y = f2tf32(xk.y); xk.z = f2tf32(xk.z); xk.w = f2tf32(xk.w);
        xv.x = f2tf32(xv.x); xv.y = f2tf32(xv.y); xv.z = f2tf32(xv.z); xv.w = f2tf32(xv.w);
        *pk = xk; *pv = xv;
    }
    __syncthreads();

    // ---- GEMM1: S[16,48] = Q @ K^T ----
    float acc[6][4] = {};
#pragma unroll
    for (int kk = 0; kk < 8; kk++) {
#pragma unroll
        for (int nt = 0; nt < 6; nt++) {
            const float* kp = ks + (qb + nt * 8 + gid) * STRIDE + kk * 8 + tig;
            mma_tf32(acc[nt], qa[kk][0], qa[kk][1], qa[kk][2], qa[kk][3],
                     bits(kp[0]), bits(kp[4]));
        }
    }

    // ---- Gate + mask in registers; D-frag -> A-frag via shuffles ----
    const int srcA = (lane & 28) | ((lane & 3) >> 1);
    const int srcB = srcA + 2;
    const bool odd = (lane & 1) != 0;
    uint32_t wa[6][4];
#pragma unroll
    for (int nt = 0; nt < 6; nt++) {
        float w[4];
#pragma unroll
        for (int e = 0; e < 4; e++) {
            const int row = (e >= 2) ? gid + 8 : gid;
            const int col = nt * 8 + 2 * tig + (e & 1);
            const int l   = qb + col;
            const int j   = s0 - (W_ - 1) + l;
            const int d   = col - row;
            const bool ok = (d >= 0) && (d < W_) && (j >= 0);
            const float bq = (e >= 2) ? bq1 : bq0;
            const float g = 1.f / (1.f + __expf(-a_sm[l] * bq));
            w[e] = f2tf32(ok ? acc[nt][e] * (SCALE * g) : 0.f);
        }
        const float s00 = __shfl_sync(0xffffffffu, w[0], srcA);
        const float s10 = __shfl_sync(0xffffffffu, w[1], srcA);
        const float s20 = __shfl_sync(0xffffffffu, w[2], srcA);
        const float s30 = __shfl_sync(0xffffffffu, w[3], srcA);
        const float s01 = __shfl_sync(0xffffffffu, w[0], srcB);
        const float s11 = __shfl_sync(0xffffffffu, w[1], srcB);
        const float s21 = __shfl_sync(0xffffffffu, w[2], srcB);
        const float s31 = __shfl_sync(0xffffffffu, w[3], srcB);
        wa[nt][0] = bits(odd ? s10 : s00);    // W[gid][tig]
        wa[nt][1] = bits(odd ? s30 : s20);    // W[gid+8][tig]
        wa[nt][2] = bits(odd ? s11 : s01);    // W[gid][tig+4]
        wa[nt][3] = bits(odd ? s31 : s21);    // W[gid+8][tig+4]
    }

    // ---- GEMM2: O[16,64] = W[16,48] @ V[48,64] (no barrier needed) ----
    float oacc[8][4] = {};
#pragma unroll
    for (int kk = 0; kk < 6; kk++) {
#pragma unroll
        for (int nt = 0; nt < 8; nt++) {
            const float* vp0 = vs + (qb + kk * 8 + tig) * STRIDE + nt * 8 + gid;
            const float* vp1 = vp0 + 4 * STRIDE;
            mma_tf32(oacc[nt], wa[kk][0], wa[kk][1], wa[kk][2], wa[kk][3],
                     bits(vp0[0]), bits(vp1[0]));
        }
    }

    // ---- Store O ----
    float* d0 = outg + headBase + (size_t)(s0 + qb + gid) * HD + 2 * tig;
    float* d1 = d0 + (size_t)8 * HD;
#pragma unroll
    for (int nt = 0; nt < 8; nt++) {
        *(float2*)(d0 + nt * 8) = make_float2(oacc[nt][0], oacc[nt][1]);
        *(float2*)(d1 + nt * 8) = make_float2(oacc[nt][2], oacc[nt][3]);
    }
}

extern "C" void kernel_launch(void* const* d_in, const int* in_sizes, int n_in,
                              void* d_out, int out_size)
{
    const float* q = (const float*)d_in[0];
    const float* k = (const float*)d_in[1];
    const float* v = (const float*)d_in[2];
    const float* a = (const float*)d_in[3];
    const float* b = (const float*)d_in[4];
    float* out = (float*)d_out;

    const int smem = SMEM_FLOATS * (int)sizeof(float);   // 52608 B
    cudaFuncSetAttribute(swa_mma5_kernel,
                         cudaFuncAttributeMaxDynamicSharedMemorySize, smem);
    dim3 grid(S_ / TS, H_, B_);
    swa_mma5_kernel<<<grid, NT, smem>>>(q, k, v, a, b, out);
}